// round 15
// baseline (speedup 1.0000x reference)
#include <cuda_runtime.h>
#include <math.h>

// Problem constants
#define BB 256
#define TT 1000
#define NN 200
#define NII 7

#define ALPHA_F 0.2f
#define OMA_F   0.8f
#define NSC_F   0.0948683292f   // 0.15*sqrt(2*0.2)

typedef unsigned long long u64;

// 205MB scratch for the precomputed input drive (allowed: static __device__)
__device__ float g_drive[(size_t)BB * TT * NN];

__device__ __forceinline__ void ffma2(u64& acc, u64 w, u64 y) {
    asm("fma.rn.f32x2 %0, %1, %2, %0;" : "+l"(acc) : "l"(w), "l"(y));
}
__device__ __forceinline__ u64 add2(u64 a, u64 b) {
    u64 s; asm("add.rn.f32x2 %0, %1, %2;" : "=l"(s) : "l"(a), "l"(b));
    return s;
}
__device__ __forceinline__ float hsum8(u64 a, u64 b, u64 c, u64 d) {
    u64 s = add2(add2(a, b), add2(c, d));
    float2 f;
    asm("mov.b64 {%0, %1}, %2;" : "=f"(f.x), "=f"(f.y) : "l"(s));
    return f.x + f.y;
}

// ============ pre-kernel: drive = |W_in| . u + b_rec ============
__global__ void drive_kernel(const float* __restrict__ u_seq,
                             const float* __restrict__ W_in_raw,
                             const float* __restrict__ b_rec) {
    int t0 = blockIdx.x * 4;
    int b  = blockIdx.y;
    int n  = threadIdx.x;
    if (n >= NN) return;
    float wia[NII];
    #pragma unroll
    for (int i = 0; i < NII; ++i) wia[i] = fabsf(__ldg(&W_in_raw[n * NII + i]));
    float br = __ldg(&b_rec[n]);
    #pragma unroll
    for (int j = 0; j < 4; ++j) {
        int t = t0 + j;
        float d = br;
        #pragma unroll
        for (int i = 0; i < NII; ++i)
            d = fmaf(wia[i], __ldg(&u_seq[((size_t)b * TT + t) * NII + i]), d);
        g_drive[((size_t)b * TT + t) * NN + n] = d;
    }
}

// ============ main persistent recurrence kernel ============
__global__ void __launch_bounds__(256, 1)
rnn_main(const float* __restrict__ y0,
         const float* __restrict__ noise,
         const float* __restrict__ W_rec,
         float* __restrict__ out)
{
    __shared__ __align__(16) float y_s[2][2][NN];   // [buf][row][neuron]

    const int tid = threadIdx.x;
    const bool act = (tid < NN);
    const int  n   = act ? tid : 0;
    const int  b0  = blockIdx.x * 2;
    const int  b1  = b0 + 1;

    float* __restrict__ yseq = out;
    float* __restrict__ yfin = out + (size_t)BB * TT * NN + (size_t)BB * TT;

    // ---- full W row in registers (200 fp32 = 100 x b64) ----
    u64 w[NN / 2];
    if (act) {
        const u64* wp = reinterpret_cast<const u64*>(W_rec + (size_t)n * NN);
        #pragma unroll
        for (int m = 0; m < NN / 2; ++m) w[m] = __ldg(&wp[m]);
    }

    float yold0 = 0.f, yold1 = 0.f;
    float nz0 = 0.f, nz1 = 0.f, dr0 = 0.f, dr1 = 0.f;
    const float* np0 = noise   + (size_t)b0 * TT * NN + n;
    const float* np1 = noise   + (size_t)b1 * TT * NN + n;
    const float* dp0 = g_drive + (size_t)b0 * TT * NN + n;
    const float* dp1 = g_drive + (size_t)b1 * TT * NN + n;
    float* yp0 = yseq + (size_t)b0 * TT * NN + n;
    float* yp1 = yseq + (size_t)b1 * TT * NN + n;

    if (act) {
        yold0 = y0[(size_t)b0 * NN + n];
        yold1 = y0[(size_t)b1 * NN + n];
        y_s[0][0][n] = yold0;
        y_s[0][1][n] = yold1;
        nz0 = __ldcs(np0); nz1 = __ldcs(np1);
        dr0 = __ldcs(dp0); dr1 = __ldcs(dp1);
    }
    __syncthreads();

    int buf = 0;
    for (int t = 0; t < TT; ++t) {
        // prefetch next step's noise + drive (4 coalesced LDGs)
        float nz0n = 0.f, nz1n = 0.f, dr0n = 0.f, dr1n = 0.f;
        if (act && (t + 1 < TT)) {
            nz0n = __ldcs(np0 + (t + 1) * NN);
            nz1n = __ldcs(np1 + (t + 1) * NN);
            dr0n = __ldcs(dp0 + (t + 1) * NN);
            dr1n = __ldcs(dp1 + (t + 1) * NN);
        }

        if (act) {
            // ---- dot: 100 LDS.128, 200 FFMA2, 8 independent chains ----
            const ulonglong2* Y0 = reinterpret_cast<const ulonglong2*>(y_s[buf][0]);
            const ulonglong2* Y1 = reinterpret_cast<const ulonglong2*>(y_s[buf][1]);
            u64 c0a = 0, c0b = 0, c0c = 0, c0d = 0;
            u64 c1a = 0, c1b = 0, c1c = 0, c1d = 0;
            #pragma unroll
            for (int m = 0; m < NN / 8; ++m) {      // 25 iters x 8 floats/row
                ulonglong2 pA = Y0[2 * m], pB = Y0[2 * m + 1];
                ulonglong2 qA = Y1[2 * m], qB = Y1[2 * m + 1];
                ffma2(c0a, w[4 * m + 0], pA.x);
                ffma2(c0b, w[4 * m + 1], pA.y);
                ffma2(c1a, w[4 * m + 0], qA.x);
                ffma2(c1b, w[4 * m + 1], qA.y);
                ffma2(c0c, w[4 * m + 2], pB.x);
                ffma2(c0d, w[4 * m + 3], pB.y);
                ffma2(c1c, w[4 * m + 2], qB.x);
                ffma2(c1d, w[4 * m + 3], qB.y);
            }
            float pre0 = hsum8(c0a, c0b, c0c, c0d);
            float pre1 = hsum8(c1a, c1b, c1c, c1d);

            // ---- epilogue: y' = 0.8 y + 0.2 relu(pre + drive) + NSC*noise ----
            float r0 = fmaxf(pre0 + dr0, 0.f);
            float r1 = fmaxf(pre1 + dr1, 0.f);
            float yn0 = fmaf(OMA_F, yold0, fmaf(ALPHA_F, r0, NSC_F * nz0));
            float yn1 = fmaf(OMA_F, yold1, fmaf(ALPHA_F, r1, NSC_F * nz1));
            y_s[buf ^ 1][0][n] = yn0;
            y_s[buf ^ 1][1][n] = yn1;
            __stcs(yp0, yn0);
            __stcs(yp1, yn1);
            yp0 += NN; yp1 += NN;
            yold0 = yn0; yold1 = yn1;
            nz0 = nz0n; nz1 = nz1n;
            dr0 = dr0n; dr1 = dr1n;
        }
        __syncthreads();
        buf ^= 1;
    }

    if (act) {
        yfin[(size_t)b0 * NN + n] = yold0;
        yfin[(size_t)b1 * NN + n] = yold1;
    }
}

// ============ post-kernel: z = sigmoid(y_seq . w_out + b_out) ============
__global__ void z_kernel(const float* __restrict__ w_out,
                         const float* __restrict__ b_out,
                         float* __restrict__ out)
{
    __shared__ float wsm[NN];
    const int tid = threadIdx.x, lane = tid & 31, wid = tid >> 5;
    for (int i = tid; i < NN; i += 256) wsm[i] = w_out[i];
    __syncthreads();

    size_t idx = (size_t)blockIdx.x * 8 + wid;      // linear (b*TT + t)
    const float* y = out + idx * NN;
    float s = 0.f;
    #pragma unroll
    for (int k = lane; k < NN; k += 32)
        s = fmaf(__ldcs(&y[k]), wsm[k], s);
    s += __shfl_xor_sync(0xFFFFFFFFu, s, 16);
    s += __shfl_xor_sync(0xFFFFFFFFu, s, 8);
    s += __shfl_xor_sync(0xFFFFFFFFu, s, 4);
    s += __shfl_xor_sync(0xFFFFFFFFu, s, 2);
    s += __shfl_xor_sync(0xFFFFFFFFu, s, 1);
    if (lane == 0) {
        float* zseq = out + (size_t)BB * TT * NN;
        zseq[idx] = 1.f / (1.f + expf(-(s + b_out[0])));
    }
}

extern "C" void kernel_launch(void* const* d_in, const int* in_sizes, int n_in,
                              void* d_out, int out_size) {
    const float* y0       = (const float*)d_in[0];
    const float* u_seq    = (const float*)d_in[1];
    const float* noise    = (const float*)d_in[2];
    const float* W_in_raw = (const float*)d_in[3];
    const float* W_rec    = (const float*)d_in[4];
    const float* b_rec    = (const float*)d_in[5];
    const float* w_out    = (const float*)d_in[6];
    const float* b_out    = (const float*)d_in[7];
    float* out = (float*)d_out;

    dim3 dgrid(TT / 4, BB);
    drive_kernel<<<dgrid, 256>>>(u_seq, W_in_raw, b_rec);
    rnn_main<<<BB / 2, 256>>>(y0, noise, W_rec, out);
    z_kernel<<<(BB * TT) / 8, 256>>>(w_out, b_out, out);
}